// round 1
// baseline (speedup 1.0000x reference)
#include <cuda_runtime.h>
#include <cuda_fp16.h>

#define SEQ   2048
#define DM    2048
#define DIN   4096
#define E2    8192      // 2*DIN
#define DTR   128
#define DST   16
#define NPROJ 160       // DTR + 2*DST
#define EPS   1e-6f

// ---------------- scratch (static device globals; no allocation) ----------------
__device__ float g_proj [SEQ * E2];    // [s][e]  e<4096: h ; e>=4096: z   (64 MB)
__device__ float g_hconv[SEQ * DIN];   // [s][d] post conv+silu                (32 MB)
__device__ float g_ssm  [SEQ * NPROJ]; // [s][160]
__device__ float g_delta[SEQ * DTR];   // [s][128] normalized delta
__device__ float g_Bm   [SEQ * DST];
__device__ float g_Cm   [SEQ * DST];
__device__ float g_dt   [SEQ * DIN];   // [s][d] softplus(dd + b_dt)           (32 MB)
__device__ float g_yg   [SEQ * DIN];   // [s][d] gated scan output             (32 MB)
__device__ float g_yn   [SEQ * DIN];   // [s][d] final-rmsnormed               (32 MB)

// ---------------- generic NT SGEMM: C[m][n] = sum_k A[m][k]*B[n][k] ----------------
// BM=BN=128, BK=8, 256 threads, 8x8 per thread (split 4+4 rows/cols for
// conflict-free LDS.128 reads).  EPI==1: softplus(acc + bias[n]).
#define BMT 128
#define BNT 128
#define BKT 8

template<int EPI>
__global__ __launch_bounds__(256) void sgemm_nt(
    const float* __restrict__ A, const float* __restrict__ B,
    const float* __restrict__ bias, float* __restrict__ C,
    int M, int N, int K)
{
    __shared__ float As[BKT][BMT];
    __shared__ float Bs[BKT][BNT];

    const int tid = threadIdx.x;
    const int bm0 = blockIdx.y * BMT;
    const int bn0 = blockIdx.x * BNT;
    const int tx = tid & 15;      // 0..15
    const int ty = tid >> 4;      // 0..15

    const int ldRow = tid >> 1;          // 0..127
    const int ldCol = (tid & 1) * 4;     // 0 or 4

    const float* Aptr = A + (size_t)(bm0 + ldRow) * K + ldCol;
    const bool bValid = (bn0 + ldRow) < N;
    const float* Bptr = B + (size_t)(bValid ? (bn0 + ldRow) : 0) * K + ldCol;

    float acc[8][8];
#pragma unroll
    for (int i = 0; i < 8; i++)
#pragma unroll
        for (int j = 0; j < 8; j++) acc[i][j] = 0.f;

    for (int k0 = 0; k0 < K; k0 += BKT) {
        float4 a4 = *(const float4*)(Aptr + k0);
        float4 b4 = bValid ? *(const float4*)(Bptr + k0) : make_float4(0.f,0.f,0.f,0.f);
        As[ldCol+0][ldRow] = a4.x; As[ldCol+1][ldRow] = a4.y;
        As[ldCol+2][ldRow] = a4.z; As[ldCol+3][ldRow] = a4.w;
        Bs[ldCol+0][ldRow] = b4.x; Bs[ldCol+1][ldRow] = b4.y;
        Bs[ldCol+2][ldRow] = b4.z; Bs[ldCol+3][ldRow] = b4.w;
        __syncthreads();

#pragma unroll
        for (int k = 0; k < BKT; k++) {
            float4 ra0 = *(const float4*)&As[k][ty * 4];
            float4 ra1 = *(const float4*)&As[k][64 + ty * 4];
            float4 rb0 = *(const float4*)&Bs[k][tx * 4];
            float4 rb1 = *(const float4*)&Bs[k][64 + tx * 4];
            float ra[8] = {ra0.x,ra0.y,ra0.z,ra0.w, ra1.x,ra1.y,ra1.z,ra1.w};
            float rb[8] = {rb0.x,rb0.y,rb0.z,rb0.w, rb1.x,rb1.y,rb1.z,rb1.w};
#pragma unroll
            for (int i = 0; i < 8; i++)
#pragma unroll
                for (int j = 0; j < 8; j++)
                    acc[i][j] = fmaf(ra[i], rb[j], acc[i][j]);
        }
        __syncthreads();
    }

#pragma unroll
    for (int i = 0; i < 8; i++) {
        int row = bm0 + (i < 4 ? ty * 4 + i : 64 + ty * 4 + (i - 4));
        if (row >= M) continue;
#pragma unroll
        for (int j = 0; j < 8; j++) {
            int col = bn0 + (j < 4 ? tx * 4 + j : 64 + tx * 4 + (j - 4));
            if (col >= N) continue;
            float v = acc[i][j];
            if (EPI == 1) {
                v += bias[col];
                v = fmaxf(v, 0.f) + log1pf(__expf(-fabsf(v)));   // stable softplus
            }
            C[(size_t)row * N + col] = v;
        }
    }
}

// ---------------- depthwise causal conv (K=4) + bias + silu ----------------
__global__ void conv_silu_kernel(const float* __restrict__ convw,
                                 const float* __restrict__ convb)
{
    int idx = blockIdx.x * blockDim.x + threadIdx.x;   // s*DIN + d
    if (idx >= SEQ * DIN) return;
    int s = idx / DIN, d = idx - s * DIN;
    float4 w = *(const float4*)(convw + d * 4);
    float acc = convb[d];
    if (s >= 3) acc = fmaf(w.x, g_proj[(size_t)(s-3) * E2 + d], acc);
    if (s >= 2) acc = fmaf(w.y, g_proj[(size_t)(s-2) * E2 + d], acc);
    if (s >= 1) acc = fmaf(w.z, g_proj[(size_t)(s-1) * E2 + d], acc);
    acc = fmaf(w.w, g_proj[(size_t)s * E2 + d], acc);
    float sg = 1.f / (1.f + __expf(-acc));
    g_hconv[idx] = acc * sg;
}

// ---------------- rmsnorm of delta / B / C (+ fp16 round-trip on B,C) ----------------
__global__ void norm_dbc_kernel(const float* __restrict__ dtw,
                                const float* __restrict__ bw,
                                const float* __restrict__ cw)
{
    int s = blockIdx.x, t = threadIdx.x;   // 128 threads
    const float* row = g_ssm + (size_t)s * NPROJ;
    float v = row[t];
    float ss = v * v;
#pragma unroll
    for (int o = 16; o > 0; o >>= 1) ss += __shfl_xor_sync(0xFFFFFFFFu, ss, o);
    __shared__ float swm[4];
    __shared__ float sbc[2];
    if ((t & 31) == 0) swm[t >> 5] = ss;
    if (t == 0) {
        float a = 0.f, b = 0.f;
#pragma unroll
        for (int i = 0; i < 16; i++) { float x = row[128 + i]; a = fmaf(x, x, a); }
#pragma unroll
        for (int i = 0; i < 16; i++) { float x = row[144 + i]; b = fmaf(x, x, b); }
        sbc[0] = a; sbc[1] = b;
    }
    __syncthreads();
    float tot = swm[0] + swm[1] + swm[2] + swm[3];
    g_delta[(size_t)s * DTR + t] = dtw[t] * v * rsqrtf(tot / 128.f + EPS);
    if (t < 16) {
        float x = row[128 + t];
        float r = bw[t] * x * rsqrtf(sbc[0] / 16.f + EPS);
        g_Bm[s * DST + t] = __half2float(__float2half(r));   // fp16 round-trip (RN)
    } else if (t < 32) {
        int i = t - 16;
        float x = row[144 + i];
        float r = cw[i] * x * rsqrtf(sbc[1] / 16.f + EPS);
        g_Cm[s * DST + i] = __half2float(__float2half(r));
    }
}

// ---------------- selective scan (sequential over l, parallel over d) ----------------
// 64 blocks x 128 threads; 2 threads per channel, 8 states each.
#define SCAN_CHUNK 128
__global__ __launch_bounds__(128) void scan_kernel(const float* __restrict__ A_log,
                                                   const float* __restrict__ Dp)
{
    const int tid  = threadIdx.x;
    const int d    = blockIdx.x * 64 + (tid >> 1);
    const int half = tid & 1;

    float A[8], st[8];
#pragma unroll
    for (int n = 0; n < 8; n++) {
        A[n]  = -__expf(A_log[d * DST + half * 8 + n]);
        st[n] = 0.f;
    }
    const float dp = Dp[d];

    __shared__ float sB[SCAN_CHUNK][DST];
    __shared__ float sC[SCAN_CHUNK][DST];

    // prefetch l = 0
    float dt_nx = g_dt[d];
    float h_nx  = g_hconv[d];
    float z_nx  = g_proj[DIN + d];

    for (int l0 = 0; l0 < SEQ; l0 += SCAN_CHUNK) {
        __syncthreads();
        for (int i = tid; i < SCAN_CHUNK * DST; i += 128) {
            sB[i >> 4][i & 15] = g_Bm[l0 * DST + i];
            sC[i >> 4][i & 15] = g_Cm[l0 * DST + i];
        }
        __syncthreads();

        for (int l = l0; l < l0 + SCAN_CHUNK; l++) {
            float dtv = dt_nx, hv = h_nx, zv = z_nx;
            int ln = l + 1;
            if (ln < SEQ) {
                dt_nx = g_dt[(size_t)ln * DIN + d];
                h_nx  = g_hconv[(size_t)ln * DIN + d];
                z_nx  = g_proj[(size_t)ln * E2 + DIN + d];
            }
            const int li = l - l0;
            const float dbh = dtv * hv;
            float y = 0.f;
#pragma unroll
            for (int n = 0; n < 8; n++) {
                float da = __expf(dtv * A[n]);
                st[n] = fmaf(da, st[n], dbh * sB[li][half * 8 + n]);
                y     = fmaf(st[n], sC[li][half * 8 + n], y);
            }
            y += __shfl_xor_sync(0xFFFFFFFFu, y, 1);
            if (half == 0) {
                float g  = y + dp * hv;
                float sg = zv / (1.f + __expf(-zv));   // silu(z)
                g_yg[(size_t)l * DIN + d] = g * sg;
            }
        }
    }
}

// ---------------- final rmsnorm over d=4096 per token ----------------
__global__ __launch_bounds__(256) void rms_final_kernel(const float* __restrict__ w)
{
    int l = blockIdx.x, t = threadIdx.x;
    float v[16];
    float ss = 0.f;
#pragma unroll
    for (int i = 0; i < 16; i++) {
        v[i] = g_yg[(size_t)l * DIN + t + i * 256];
        ss = fmaf(v[i], v[i], ss);
    }
#pragma unroll
    for (int o = 16; o > 0; o >>= 1) ss += __shfl_xor_sync(0xFFFFFFFFu, ss, o);
    __shared__ float swm[8];
    if ((t & 31) == 0) swm[t >> 5] = ss;
    __syncthreads();
    float tot = 0.f;
#pragma unroll
    for (int i = 0; i < 8; i++) tot += swm[i];
    float inv = rsqrtf(tot / (float)DIN + EPS);
#pragma unroll
    for (int i = 0; i < 16; i++) {
        int d = t + i * 256;
        g_yn[(size_t)l * DIN + d] = w[d] * v[i] * inv;
    }
}

// ---------------- launch ----------------
extern "C" void kernel_launch(void* const* d_in, const int* in_sizes, int n_in,
                              void* d_out, int out_size)
{
    const float* x       = (const float*)d_in[0];
    // d_in[1] = gate (unused by reference)
    const float* W_in    = (const float*)d_in[2];
    const float* conv_w  = (const float*)d_in[3];
    const float* conv_b  = (const float*)d_in[4];
    const float* W_x     = (const float*)d_in[5];
    const float* W_dt    = (const float*)d_in[6];
    const float* b_dt    = (const float*)d_in[7];
    const float* A_log   = (const float*)d_in[8];
    const float* Dp      = (const float*)d_in[9];
    const float* dt_ln   = (const float*)d_in[10];
    const float* B_ln    = (const float*)d_in[11];
    const float* C_ln    = (const float*)d_in[12];
    const float* scan_ln = (const float*)d_in[13];
    const float* W_out   = (const float*)d_in[14];
    float* out = (float*)d_out;

    float *p_proj, *p_hconv, *p_ssm, *p_delta, *p_dt, *p_yn;
    cudaGetSymbolAddress((void**)&p_proj,  g_proj);
    cudaGetSymbolAddress((void**)&p_hconv, g_hconv);
    cudaGetSymbolAddress((void**)&p_ssm,   g_ssm);
    cudaGetSymbolAddress((void**)&p_delta, g_delta);
    cudaGetSymbolAddress((void**)&p_dt,    g_dt);
    cudaGetSymbolAddress((void**)&p_yn,    g_yn);

    // 1) in-projection: proj[s][e] = sum_d x[s][d] * W_in[e][d]   (M=2048,N=8192,K=2048)
    sgemm_nt<0><<<dim3(E2 / BNT, SEQ / BMT), 256>>>(x, W_in, nullptr, p_proj, SEQ, E2, DM);

    // 2) causal depthwise conv + silu
    conv_silu_kernel<<<(SEQ * DIN + 255) / 256, 256>>>(conv_w, conv_b);

    // 3) x-projection: ssm_p[s][e'] = sum_d hconv[s][d] * W_x[e'][d]  (N=160)
    sgemm_nt<0><<<dim3((NPROJ + BNT - 1) / BNT, SEQ / BMT), 256>>>(p_hconv, W_x, nullptr, p_ssm, SEQ, NPROJ, DIN);

    // 4) rmsnorm of delta / B / C (B,C with fp16 round-trip)
    norm_dbc_kernel<<<SEQ, 128>>>(dt_ln, B_ln, C_ln);

    // 5) dt = softplus(delta @ W_dt^T + b_dt)  (M=2048,N=4096,K=128)
    sgemm_nt<1><<<dim3(DIN / BNT, SEQ / BMT), 256>>>(p_delta, W_dt, b_dt, p_dt, SEQ, DIN, DTR);

    // 6) selective scan + D-skip + silu(z) gating
    scan_kernel<<<64, 128>>>(A_log, Dp);

    // 7) final rmsnorm over channels
    rms_final_kernel<<<SEQ, 256>>>(scan_ln);

    // 8) out-projection: out[s][m] = sum_d yn[s][d] * W_out[m][d] (M=2048,N=2048,K=4096)
    sgemm_nt<0><<<dim3(DM / BNT, SEQ / BMT), 256>>>(p_yn, W_out, nullptr, out, SEQ, DM, DIN);
}

// round 4
// speedup vs baseline: 1.5037x; 1.5037x over previous
#include <cuda_runtime.h>
#include <cuda_fp16.h>
#include <cuda_bf16.h>
#include <cstdint>

#define SEQ   2048
#define DM    2048
#define DIN   4096
#define E2    8192      // 2*DIN
#define DTR   128
#define DST   16
#define NPROJ 160       // DTR + 2*DST
#define EPS   1e-6f

// ---------------- scratch (static device globals; no allocation) ----------------
__device__ float g_proj [SEQ * E2];
__device__ float g_hconv[SEQ * DIN];
__device__ float g_ssm  [SEQ * NPROJ];
__device__ float g_delta[SEQ * DTR];
__device__ float g_Bm   [SEQ * DST];
__device__ float g_Cm   [SEQ * DST];
__device__ float g_dt   [SEQ * DIN];
__device__ float g_yg   [SEQ * DIN];
__device__ float g_yn   [SEQ * DIN];

// ============================================================================
// bf16x3 split-precision tensor-core NT GEMM:  C[m][n] = sum_k A[m][k]*B[n][k]
// x = hi + lo (bf16 each); C += hi*hi + hi*lo + lo*hi  => ~fp32 accuracy.
// BM=BN=128, BK=16, 256 threads (8 warps 2x4), warp tile 64x32,
// mma.sync.m16n8k16.row.col.f32.bf16.bf16.f32, double-buffered dynamic smem.
// k-permuted smem layout: [0,1,8,9, 2,3,10,11, 4,5,12,13, 6,7,14,15]
//   -> each fragment (k,k+1,k+8,k+9) is one aligned LDS.64.
// Row stride 24 words (48 bf16) => conflict-free 64-bit loads.
// Requires M%128==0, N%128==0, K%16==0.
// ============================================================================
#define TBM 128
#define TBN 128
#define TBK 16
#define SW  24                    // uint32 words per smem row
#define PERARR (TBM * SW)         // 3072 words per plane
#define SMEM_BYTES (2 * 4 * PERARR * 4)   // 98304

__device__ __forceinline__ uint32_t pack_bf2(__nv_bfloat16 a, __nv_bfloat16 b) {
    return (uint32_t)__bfloat16_as_ushort(a) | ((uint32_t)__bfloat16_as_ushort(b) << 16);
}

#define MMA_BF16(acc, a0,a1,a2,a3, b0,b1)                                     \
    asm volatile(                                                             \
        "mma.sync.aligned.m16n8k16.row.col.f32.bf16.bf16.f32 "                \
        "{%0,%1,%2,%3}, {%4,%5,%6,%7}, {%8,%9}, {%0,%1,%2,%3};\n"             \
        : "+f"(acc[0]), "+f"(acc[1]), "+f"(acc[2]), "+f"(acc[3])              \
        : "r"(a0), "r"(a1), "r"(a2), "r"(a3), "r"(b0), "r"(b1))

__global__ __launch_bounds__(256) void bf16x3_gemm_nt(
    const float* __restrict__ A, const float* __restrict__ B,
    float* __restrict__ C, int M, int N, int K)
{
    extern __shared__ uint32_t sm[];

    const int tid  = threadIdx.x;
    const int bm0  = blockIdx.y * TBM;
    const int bn0  = blockIdx.x * TBN;
    const int warp = tid >> 5, lane = tid & 31;
    const int g  = lane >> 2;
    const int t4 = lane & 3;
    const int mw = (warp >> 2) * 64;
    const int nw = (warp & 3) * 32;

    const int r0 = tid >> 2;      // 0..63
    const int q  = tid & 3;       // k-quad
    const int w0 = (q & 1) * 4 + (q >> 1);   // permuted word slot for (4q,4q+1)

    float4 pfA[2], pfB[2];
    auto gload = [&](int k0) {
        pfA[0] = *(const float4*)(A + (size_t)(bm0 + r0     ) * K + k0 + q * 4);
        pfA[1] = *(const float4*)(A + (size_t)(bm0 + r0 + 64) * K + k0 + q * 4);
        pfB[0] = *(const float4*)(B + (size_t)(bn0 + r0     ) * K + k0 + q * 4);
        pfB[1] = *(const float4*)(B + (size_t)(bn0 + r0 + 64) * K + k0 + q * 4);
    };

    auto put = [&](uint32_t* H, uint32_t* L, int row, const float4& v) {
        __nv_bfloat16 hx = __float2bfloat16_rn(v.x);
        __nv_bfloat16 hy = __float2bfloat16_rn(v.y);
        __nv_bfloat16 hz = __float2bfloat16_rn(v.z);
        __nv_bfloat16 hw = __float2bfloat16_rn(v.w);
        __nv_bfloat16 lx = __float2bfloat16_rn(v.x - __bfloat162float(hx));
        __nv_bfloat16 ly = __float2bfloat16_rn(v.y - __bfloat162float(hy));
        __nv_bfloat16 lz = __float2bfloat16_rn(v.z - __bfloat162float(hz));
        __nv_bfloat16 lw = __float2bfloat16_rn(v.w - __bfloat162float(hw));
        int base = row * SW;
        H[base + w0]     = pack_bf2(hx, hy);
        H[base + w0 + 2] = pack_bf2(hz, hw);
        L[base + w0]     = pack_bf2(lx, ly);
        L[base + w0 + 2] = pack_bf2(lz, lw);
    };

    auto sstore = [&](int buf) {
        uint32_t* Ah = sm + buf * 4 * PERARR;
        uint32_t* Al = Ah + PERARR;
        uint32_t* Bh = Al + PERARR;
        uint32_t* Bl = Bh + PERARR;
        put(Ah, Al, r0,      pfA[0]);
        put(Ah, Al, r0 + 64, pfA[1]);
        put(Bh, Bl, r0,      pfB[0]);
        put(Bh, Bl, r0 + 64, pfB[1]);
    };

    float acc[4][4][4];
#pragma unroll
    for (int mt = 0; mt < 4; mt++)
#pragma unroll
        for (int nt = 0; nt < 4; nt++)
#pragma unroll
            for (int r = 0; r < 4; r++) acc[mt][nt][r] = 0.f;

    const int nIter = K / TBK;
    gload(0);
    sstore(0);
    __syncthreads();

#pragma unroll 1
    for (int it = 0; it < nIter; ++it) {
        const int buf = it & 1;
        if (it + 1 < nIter) gload((it + 1) * TBK);

        const uint32_t* Ah = sm + buf * 4 * PERARR;
        const uint32_t* Al = Ah + PERARR;
        const uint32_t* Bh = Al + PERARR;
        const uint32_t* Bl = Bh + PERARR;

        uint32_t ah[4][4], al[4][4], bh[4][2], bl[4][2];
#pragma unroll
        for (int mt = 0; mt < 4; mt++) {
            int rb = mw + mt * 16;
            uint2 x0 = *(const uint2*)&Ah[(rb + g    ) * SW + 2 * t4];
            uint2 x1 = *(const uint2*)&Ah[(rb + g + 8) * SW + 2 * t4];
            uint2 y0 = *(const uint2*)&Al[(rb + g    ) * SW + 2 * t4];
            uint2 y1 = *(const uint2*)&Al[(rb + g + 8) * SW + 2 * t4];
            ah[mt][0] = x0.x; ah[mt][2] = x0.y;
            ah[mt][1] = x1.x; ah[mt][3] = x1.y;
            al[mt][0] = y0.x; al[mt][2] = y0.y;
            al[mt][1] = y1.x; al[mt][3] = y1.y;
        }
#pragma unroll
        for (int nt = 0; nt < 4; nt++) {
            int cb = nw + nt * 8;
            uint2 z  = *(const uint2*)&Bh[(cb + g) * SW + 2 * t4];
            uint2 zl = *(const uint2*)&Bl[(cb + g) * SW + 2 * t4];
            bh[nt][0] = z.x;  bh[nt][1] = z.y;
            bl[nt][0] = zl.x; bl[nt][1] = zl.y;
        }
#pragma unroll
        for (int mt = 0; mt < 4; mt++)
#pragma unroll
            for (int nt = 0; nt < 4; nt++) {
                MMA_BF16(acc[mt][nt], al[mt][0],al[mt][1],al[mt][2],al[mt][3],
                                      bh[nt][0],bh[nt][1]);
                MMA_BF16(acc[mt][nt], ah[mt][0],ah[mt][1],ah[mt][2],ah[mt][3],
                                      bl[nt][0],bl[nt][1]);
                MMA_BF16(acc[mt][nt], ah[mt][0],ah[mt][1],ah[mt][2],ah[mt][3],
                                      bh[nt][0],bh[nt][1]);
            }

        if (it + 1 < nIter) sstore((it + 1) & 1);
        __syncthreads();
    }

#pragma unroll
    for (int mt = 0; mt < 4; mt++) {
        int row = bm0 + mw + mt * 16 + g;
#pragma unroll
        for (int nt = 0; nt < 4; nt++) {
            int col = bn0 + nw + nt * 8 + t4 * 2;
            *(float2*)(C + (size_t)row * N + col) =
                make_float2(acc[mt][nt][0], acc[mt][nt][1]);
            *(float2*)(C + (size_t)(row + 8) * N + col) =
                make_float2(acc[mt][nt][2], acc[mt][nt][3]);
        }
    }
}

// ---------------- generic NT SGEMM (FFMA) for the skinny GEMMs ----------------
#define BMT 128
#define BNT 128
#define BKT 8

template<int EPI>
__global__ __launch_bounds__(256) void sgemm_nt(
    const float* __restrict__ A, const float* __restrict__ B,
    const float* __restrict__ bias, float* __restrict__ C,
    int M, int N, int K)
{
    __shared__ float As[BKT][BMT];
    __shared__ float Bs[BKT][BNT];

    const int tid = threadIdx.x;
    const int bm0 = blockIdx.y * BMT;
    const int bn0 = blockIdx.x * BNT;
    const int tx = tid & 15;
    const int ty = tid >> 4;

    const int ldRow = tid >> 1;
    const int ldCol = (tid & 1) * 4;

    const float* Aptr = A + (size_t)(bm0 + ldRow) * K + ldCol;
    const bool bValid = (bn0 + ldRow) < N;
    const float* Bptr = B + (size_t)(bValid ? (bn0 + ldRow) : 0) * K + ldCol;

    float acc[8][8];
#pragma unroll
    for (int i = 0; i < 8; i++)
#pragma unroll
        for (int j = 0; j < 8; j++) acc[i][j] = 0.f;

    for (int k0 = 0; k0 < K; k0 += BKT) {
        float4 a4 = *(const float4*)(Aptr + k0);
        float4 b4 = bValid ? *(const float4*)(Bptr + k0) : make_float4(0.f,0.f,0.f,0.f);
        As[ldCol+0][ldRow] = a4.x; As[ldCol+1][ldRow] = a4.y;
        As[ldCol+2][ldRow] = a4.z; As[ldCol+3][ldRow] = a4.w;
        Bs[ldCol+0][ldRow] = b4.x; Bs[ldCol+1][ldRow] = b4.y;
        Bs[ldCol+2][ldRow] = b4.z; Bs[ldCol+3][ldRow] = b4.w;
        __syncthreads();

#pragma unroll
        for (int k = 0; k < BKT; k++) {
            float4 ra0 = *(const float4*)&As[k][ty * 4];
            float4 ra1 = *(const float4*)&As[k][64 + ty * 4];
            float4 rb0 = *(const float4*)&Bs[k][tx * 4];
            float4 rb1 = *(const float4*)&Bs[k][64 + tx * 4];
            float ra[8] = {ra0.x,ra0.y,ra0.z,ra0.w, ra1.x,ra1.y,ra1.z,ra1.w};
            float rb[8] = {rb0.x,rb0.y,rb0.z,rb0.w, rb1.x,rb1.y,rb1.z,rb1.w};
#pragma unroll
            for (int i = 0; i < 8; i++)
#pragma unroll
                for (int j = 0; j < 8; j++)
                    acc[i][j] = fmaf(ra[i], rb[j], acc[i][j]);
        }
        __syncthreads();
    }

#pragma unroll
    for (int i = 0; i < 8; i++) {
        int row = bm0 + (i < 4 ? ty * 4 + i : 64 + ty * 4 + (i - 4));
        if (row >= M) continue;
#pragma unroll
        for (int j = 0; j < 8; j++) {
            int col = bn0 + (j < 4 ? tx * 4 + j : 64 + tx * 4 + (j - 4));
            if (col >= N) continue;
            float v = acc[i][j];
            if (EPI == 1) {
                v += bias[col];
                v = fmaxf(v, 0.f) + log1pf(__expf(-fabsf(v)));
            }
            C[(size_t)row * N + col] = v;
        }
    }
}

// ---------------- depthwise causal conv (K=4) + bias + silu ----------------
__global__ void conv_silu_kernel(const float* __restrict__ convw,
                                 const float* __restrict__ convb)
{
    int idx = blockIdx.x * blockDim.x + threadIdx.x;
    if (idx >= SEQ * DIN) return;
    int s = idx / DIN, d = idx - s * DIN;
    float4 w = *(const float4*)(convw + d * 4);
    float acc = convb[d];
    if (s >= 3) acc = fmaf(w.x, g_proj[(size_t)(s-3) * E2 + d], acc);
    if (s >= 2) acc = fmaf(w.y, g_proj[(size_t)(s-2) * E2 + d], acc);
    if (s >= 1) acc = fmaf(w.z, g_proj[(size_t)(s-1) * E2 + d], acc);
    acc = fmaf(w.w, g_proj[(size_t)s * E2 + d], acc);
    float sg = 1.f / (1.f + __expf(-acc));
    g_hconv[idx] = acc * sg;
}

// ---------------- rmsnorm of delta / B / C (+ fp16 round-trip on B,C) ----------------
__global__ void norm_dbc_kernel(const float* __restrict__ dtw,
                                const float* __restrict__ bw,
                                const float* __restrict__ cw)
{
    int s = blockIdx.x, t = threadIdx.x;
    const float* row = g_ssm + (size_t)s * NPROJ;
    float v = row[t];
    float ss = v * v;
#pragma unroll
    for (int o = 16; o > 0; o >>= 1) ss += __shfl_xor_sync(0xFFFFFFFFu, ss, o);
    __shared__ float swm[4];
    __shared__ float sbc[2];
    if ((t & 31) == 0) swm[t >> 5] = ss;
    if (t == 0) {
        float a = 0.f, b = 0.f;
#pragma unroll
        for (int i = 0; i < 16; i++) { float x = row[128 + i]; a = fmaf(x, x, a); }
#pragma unroll
        for (int i = 0; i < 16; i++) { float x = row[144 + i]; b = fmaf(x, x, b); }
        sbc[0] = a; sbc[1] = b;
    }
    __syncthreads();
    float tot = swm[0] + swm[1] + swm[2] + swm[3];
    g_delta[(size_t)s * DTR + t] = dtw[t] * v * rsqrtf(tot / 128.f + EPS);
    if (t < 16) {
        float x = row[128 + t];
        float r = bw[t] * x * rsqrtf(sbc[0] / 16.f + EPS);
        g_Bm[s * DST + t] = __half2float(__float2half(r));
    } else if (t < 32) {
        int i = t - 16;
        float x = row[144 + i];
        float r = cw[i] * x * rsqrtf(sbc[1] / 16.f + EPS);
        g_Cm[s * DST + i] = __half2float(__float2half(r));
    }
}

// ---------------- selective scan (128 blocks x 64 threads; 2 thr/channel) ----------------
#define SCAN_CHUNK 128
__global__ __launch_bounds__(64) void scan_kernel(const float* __restrict__ A_log,
                                                  const float* __restrict__ Dp)
{
    const int tid  = threadIdx.x;
    const int d    = blockIdx.x * 32 + (tid >> 1);
    const int half = tid & 1;

    float A[8], st[8];
#pragma unroll
    for (int n = 0; n < 8; n++) {
        A[n]  = -__expf(A_log[d * DST + half * 8 + n]);
        st[n] = 0.f;
    }
    const float dp = Dp[d];

    __shared__ float sB[SCAN_CHUNK][DST];
    __shared__ float sC[SCAN_CHUNK][DST];

    float dt_nx = g_dt[d];
    float h_nx  = g_hconv[d];
    float z_nx  = g_proj[DIN + d];

    for (int l0 = 0; l0 < SEQ; l0 += SCAN_CHUNK) {
        __syncthreads();
        for (int i = tid; i < SCAN_CHUNK * DST; i += 64) {
            sB[i >> 4][i & 15] = g_Bm[l0 * DST + i];
            sC[i >> 4][i & 15] = g_Cm[l0 * DST + i];
        }
        __syncthreads();

        for (int l = l0; l < l0 + SCAN_CHUNK; l++) {
            float dtv = dt_nx, hv = h_nx, zv = z_nx;
            int ln = l + 1;
            if (ln < SEQ) {
                dt_nx = g_dt[(size_t)ln * DIN + d];
                h_nx  = g_hconv[(size_t)ln * DIN + d];
                z_nx  = g_proj[(size_t)ln * E2 + DIN + d];
            }
            const int li = l - l0;
            const float dbh = dtv * hv;
            float y = 0.f;
#pragma unroll
            for (int n = 0; n < 8; n++) {
                float da = __expf(dtv * A[n]);
                st[n] = fmaf(da, st[n], dbh * sB[li][half * 8 + n]);
                y     = fmaf(st[n], sC[li][half * 8 + n], y);
            }
            y += __shfl_xor_sync(0xFFFFFFFFu, y, 1);
            if (half == 0) {
                float gg = y + dp * hv;
                float sg = zv / (1.f + __expf(-zv));
                g_yg[(size_t)l * DIN + d] = gg * sg;
            }
        }
    }
}

// ---------------- final rmsnorm over d=4096 per token ----------------
__global__ __launch_bounds__(256) void rms_final_kernel(const float* __restrict__ w)
{
    int l = blockIdx.x, t = threadIdx.x;
    float v[16];
    float ss = 0.f;
#pragma unroll
    for (int i = 0; i < 16; i++) {
        v[i] = g_yg[(size_t)l * DIN + t + i * 256];
        ss = fmaf(v[i], v[i], ss);
    }
#pragma unroll
    for (int o = 16; o > 0; o >>= 1) ss += __shfl_xor_sync(0xFFFFFFFFu, ss, o);
    __shared__ float swm[8];
    if ((t & 31) == 0) swm[t >> 5] = ss;
    __syncthreads();
    float tot = 0.f;
#pragma unroll
    for (int i = 0; i < 8; i++) tot += swm[i];
    float inv = rsqrtf(tot / (float)DIN + EPS);
#pragma unroll
    for (int i = 0; i < 16; i++) {
        int d = t + i * 256;
        g_yn[(size_t)l * DIN + d] = w[d] * v[i] * inv;
    }
}

// ---------------- launch ----------------
extern "C" void kernel_launch(void* const* d_in, const int* in_sizes, int n_in,
                              void* d_out, int out_size)
{
    const float* x       = (const float*)d_in[0];
    const float* W_in    = (const float*)d_in[2];
    const float* conv_w  = (const float*)d_in[3];
    const float* conv_b  = (const float*)d_in[4];
    const float* W_x     = (const float*)d_in[5];
    const float* W_dt    = (const float*)d_in[6];
    const float* b_dt    = (const float*)d_in[7];
    const float* A_log   = (const float*)d_in[8];
    const float* Dp      = (const float*)d_in[9];
    const float* dt_ln   = (const float*)d_in[10];
    const float* B_ln    = (const float*)d_in[11];
    const float* C_ln    = (const float*)d_in[12];
    const float* scan_ln = (const float*)d_in[13];
    const float* W_out   = (const float*)d_in[14];
    float* out = (float*)d_out;

    float *p_proj, *p_hconv, *p_ssm, *p_delta, *p_dt, *p_yn;
    cudaGetSymbolAddress((void**)&p_proj,  g_proj);
    cudaGetSymbolAddress((void**)&p_hconv, g_hconv);
    cudaGetSymbolAddress((void**)&p_ssm,   g_ssm);
    cudaGetSymbolAddress((void**)&p_delta, g_delta);
    cudaGetSymbolAddress((void**)&p_dt,    g_dt);
    cudaGetSymbolAddress((void**)&p_yn,    g_yn);

    cudaFuncSetAttribute(bf16x3_gemm_nt,
                         cudaFuncAttributeMaxDynamicSharedMemorySize, SMEM_BYTES);

    // 1) in-projection (bf16x3 tensor cores): M=2048, N=8192, K=2048
    bf16x3_gemm_nt<<<dim3(E2 / TBN, SEQ / TBM), 256, SMEM_BYTES>>>(x, W_in, p_proj, SEQ, E2, DM);

    // 2) causal depthwise conv + silu
    conv_silu_kernel<<<(SEQ * DIN + 255) / 256, 256>>>(conv_w, conv_b);

    // 3) x-projection (FFMA): N=160, K=4096
    sgemm_nt<0><<<dim3((NPROJ + BNT - 1) / BNT, SEQ / BMT), 256>>>(p_hconv, W_x, nullptr, p_ssm, SEQ, NPROJ, DIN);

    // 4) rmsnorm of delta / B / C
    norm_dbc_kernel<<<SEQ, 128>>>(dt_ln, B_ln, C_ln);

    // 5) dt = softplus(delta @ W_dt^T + b_dt)  (FFMA, K=128)
    sgemm_nt<1><<<dim3(DIN / BNT, SEQ / BMT), 256>>>(p_delta, W_dt, b_dt, p_dt, SEQ, DIN, DTR);

    // 6) selective scan
    scan_kernel<<<128, 64>>>(A_log, Dp);

    // 7) final rmsnorm
    rms_final_kernel<<<SEQ, 256>>>(scan_ln);

    // 8) out-projection (bf16x3 tensor cores): M=2048, N=2048, K=4096
    bf16x3_gemm_nt<<<dim3(DM / TBN, SEQ / TBM), 256, SMEM_BYTES>>>(p_yn, W_out, out, SEQ, DM, DIN);
}